// round 2
// baseline (speedup 1.0000x reference)
#include <cuda_runtime.h>

#define N_DATA 1024
#define D_IN   256
#define H_DIM  384
#define C_OUT  10
#define M_IND  128
#define NT_PTS 256
#define SCALE_K (1.0f/1024.0f)
#define JITTER_K 1e-3f

// ---------------- device scratch ----------------
__device__ float g_HX[N_DATA*H_DIM];
__device__ float g_SX[N_DATA*H_DIM];
__device__ float g_HZ[M_IND*H_DIM];
__device__ float g_SZ[M_IND*H_DIM];
__device__ float g_HT[NT_PTS*H_DIM];
__device__ float g_ST[NT_PTS*H_DIM];
__device__ float g_LAM[N_DATA*C_OUT];
__device__ float g_W2SQT[C_OUT*H_DIM];
__device__ float g_Pzx[M_IND*N_DATA];
__device__ float g_Qzx[M_IND*N_DATA];
__device__ float g_Pzz[M_IND*M_IND];
__device__ float g_Qzz[M_IND*M_IND];
__device__ float g_Ptz[NT_PTS*M_IND];
__device__ float g_Qtz[NT_PTS*M_IND];
__device__ float g_Ptt[NT_PTS];
__device__ float g_Qtt[NT_PTS];
__device__ float g_Kzx[C_OUT*M_IND*N_DATA];
__device__ float g_Kzz[C_OUT*M_IND*M_IND];   // overwritten by its Cholesky L
__device__ float g_Bm [C_OUT*M_IND*M_IND];   // overwritten by its Cholesky L
__device__ float g_Ktz[C_OUT*NT_PTS*M_IND];
__device__ float g_Kttd[C_OUT*NT_PTS];
__device__ float g_alpha[C_OUT*M_IND];
__device__ float g_cvec[C_OUT*M_IND];
__device__ float g_SSZ[C_OUT*NT_PTS];
__device__ float g_SSB[C_OUT*NT_PTS];

// ---------------- prep: w2^2 transposed [i][k] ----------------
__global__ void prep_kernel(const float* __restrict__ W2) {
    int idx = blockIdx.x*256 + threadIdx.x;         // 3840 exact
    if (idx >= H_DIM*C_OUT) return;
    int k = idx / C_OUT, i = idx % C_OUT;
    float w = W2[idx];
    g_W2SQT[i*H_DIM + k] = w*w;
}

// ---------------- forward: H = tanh(In@W1 + b1), S = 1-H^2 ----------------
__global__ void fwd_kernel(const float* __restrict__ In, const float* __restrict__ W1,
                           const float* __restrict__ b1,
                           float* __restrict__ Hout, float* __restrict__ Sout) {
    __shared__ __align__(16) float As[16][68];
    __shared__ __align__(16) float Bs[16][68];
    const int tid = threadIdx.x;
    const int tx = tid & 15, ty = tid >> 4;
    const int bm = blockIdx.y * 64, bn = blockIdx.x * 64;
    float acc[4][4] = {};
    for (int k0 = 0; k0 < D_IN; k0 += 16) {
        {
            int ml = tid >> 2, kq = (tid & 3) << 2;
            float4 v = *reinterpret_cast<const float4*>(&In[(bm+ml)*D_IN + k0 + kq]);
            As[kq+0][ml] = v.x; As[kq+1][ml] = v.y; As[kq+2][ml] = v.z; As[kq+3][ml] = v.w;
        }
        {
            int kl = tid >> 4, nq = (tid & 15) << 2;
            float4 v = *reinterpret_cast<const float4*>(&W1[(k0+kl)*H_DIM + bn + nq]);
            *reinterpret_cast<float4*>(&Bs[kl][nq]) = v;
        }
        __syncthreads();
        #pragma unroll
        for (int kk = 0; kk < 16; ++kk) {
            float4 a4 = *reinterpret_cast<const float4*>(&As[kk][ty*4]);
            float4 b4 = *reinterpret_cast<const float4*>(&Bs[kk][tx*4]);
            float a[4] = {a4.x,a4.y,a4.z,a4.w}, b[4] = {b4.x,b4.y,b4.z,b4.w};
            #pragma unroll
            for (int u = 0; u < 4; ++u)
                #pragma unroll
                for (int v = 0; v < 4; ++v) acc[u][v] = fmaf(a[u], b[v], acc[u][v]);
        }
        __syncthreads();
    }
    #pragma unroll
    for (int u = 0; u < 4; ++u) {
        int m = bm + ty*4 + u;
        #pragma unroll
        for (int v = 0; v < 4; ++v) {
            int n = bn + tx*4 + v;
            float h = tanhf(acc[u][v] + b1[n]);
            Hout[m*H_DIM + n] = h;
            Sout[m*H_DIM + n] = 1.0f - h*h;
        }
    }
}

// ---------------- lambda1 = F + Y ----------------
__global__ void lam_kernel(const float* __restrict__ Y, const float* __restrict__ W2,
                           const float* __restrict__ b2) {
    int warp = threadIdx.x >> 5, lane = threadIdx.x & 31;
    int row = blockIdx.x * 8 + warp;
    float h[12];
    #pragma unroll
    for (int r = 0; r < 12; ++r) h[r] = g_HX[row*H_DIM + lane + r*32];
    #pragma unroll
    for (int c = 0; c < C_OUT; ++c) {
        float acc = 0.f;
        #pragma unroll
        for (int r = 0; r < 12; ++r) acc += h[r] * W2[(lane + r*32)*C_OUT + c];
        #pragma unroll
        for (int o = 16; o; o >>= 1) acc += __shfl_down_sync(0xffffffffu, acc, o);
        if (lane == 0) g_LAM[row*C_OUT + c] = acc + b2[c] + Y[row*C_OUT + c];
    }
}

// ---------------- P = Ha@Hb^T + 1 ; Q = 1 + Xa@Xb^T ----------------
__global__ void pq_kernel(const float* __restrict__ Fa, const float* __restrict__ Fb,
                          const float* __restrict__ Xa, const float* __restrict__ Xb,
                          float* __restrict__ P, float* __restrict__ Q, int N) {
    __shared__ __align__(16) float As[16][68];
    __shared__ __align__(16) float Bs[16][68];
    const int tid = threadIdx.x;
    const int tx = tid & 15, ty = tid >> 4;
    const int bm = blockIdx.y * 64, bn = blockIdx.x * 64;
    const int l4 = tid >> 2, kq = (tid & 3) << 2;
    float acc1[4][4] = {}, acc2[4][4] = {};
    for (int k0 = 0; k0 < H_DIM; k0 += 16) {
        float4 av = *reinterpret_cast<const float4*>(&Fa[(bm+l4)*H_DIM + k0 + kq]);
        float4 bv = *reinterpret_cast<const float4*>(&Fb[(bn+l4)*H_DIM + k0 + kq]);
        As[kq+0][l4]=av.x; As[kq+1][l4]=av.y; As[kq+2][l4]=av.z; As[kq+3][l4]=av.w;
        Bs[kq+0][l4]=bv.x; Bs[kq+1][l4]=bv.y; Bs[kq+2][l4]=bv.z; Bs[kq+3][l4]=bv.w;
        __syncthreads();
        #pragma unroll
        for (int kk = 0; kk < 16; ++kk) {
            float4 a4 = *reinterpret_cast<const float4*>(&As[kk][ty*4]);
            float4 b4 = *reinterpret_cast<const float4*>(&Bs[kk][tx*4]);
            float a[4] = {a4.x,a4.y,a4.z,a4.w}, b[4] = {b4.x,b4.y,b4.z,b4.w};
            #pragma unroll
            for (int u = 0; u < 4; ++u)
                #pragma unroll
                for (int v = 0; v < 4; ++v) acc1[u][v] = fmaf(a[u], b[v], acc1[u][v]);
        }
        __syncthreads();
    }
    for (int k0 = 0; k0 < D_IN; k0 += 16) {
        float4 av = *reinterpret_cast<const float4*>(&Xa[(bm+l4)*D_IN + k0 + kq]);
        float4 bv = *reinterpret_cast<const float4*>(&Xb[(bn+l4)*D_IN + k0 + kq]);
        As[kq+0][l4]=av.x; As[kq+1][l4]=av.y; As[kq+2][l4]=av.z; As[kq+3][l4]=av.w;
        Bs[kq+0][l4]=bv.x; Bs[kq+1][l4]=bv.y; Bs[kq+2][l4]=bv.z; Bs[kq+3][l4]=bv.w;
        __syncthreads();
        #pragma unroll
        for (int kk = 0; kk < 16; ++kk) {
            float4 a4 = *reinterpret_cast<const float4*>(&As[kk][ty*4]);
            float4 b4 = *reinterpret_cast<const float4*>(&Bs[kk][tx*4]);
            float a[4] = {a4.x,a4.y,a4.z,a4.w}, b[4] = {b4.x,b4.y,b4.z,b4.w};
            #pragma unroll
            for (int u = 0; u < 4; ++u)
                #pragma unroll
                for (int v = 0; v < 4; ++v) acc2[u][v] = fmaf(a[u], b[v], acc2[u][v]);
        }
        __syncthreads();
    }
    #pragma unroll
    for (int u = 0; u < 4; ++u) {
        int m = bm + ty*4 + u;
        #pragma unroll
        for (int v = 0; v < 4; ++v) {
            int n = bn + tx*4 + v;
            P[(size_t)m*N + n] = acc1[u][v] + 1.0f;
            Q[(size_t)m*N + n] = acc2[u][v] + 1.0f;
        }
    }
}

// ---------------- diag P/Q for test points ----------------
__global__ void pqtt_kernel(const float* __restrict__ Xt) {
    int t = threadIdx.x;
    float ph = 0.f, qx = 0.f;
    const float* hr = g_HT + t*H_DIM;
    #pragma unroll 8
    for (int k = 0; k < H_DIM; ++k) ph += hr[k]*hr[k];
    const float* xr = Xt + t*D_IN;
    #pragma unroll 8
    for (int k = 0; k < D_IN; ++k) qx += xr[k]*xr[k];
    g_Ptt[t] = ph + 1.0f;
    g_Qtt[t] = qx + 1.0f;
}

// ---------------- K_i = SCALE*(P + Q * (Sa*w2sq_i)@Sb^T) ----------------
__global__ void kbuild_kernel(const float* __restrict__ Sa, const float* __restrict__ Sb,
                              const float* __restrict__ P, const float* __restrict__ Q,
                              float* __restrict__ Kout, int M, int N, int addJitter) {
    __shared__ __align__(16) float As[16][68];
    __shared__ __align__(16) float Bs[16][68];
    const int i = blockIdx.z;
    const int tid = threadIdx.x;
    const int tx = tid & 15, ty = tid >> 4;
    const int bm = blockIdx.y * 64, bn = blockIdx.x * 64;
    const int l4 = tid >> 2, kq = (tid & 3) << 2;
    const float* wrow = g_W2SQT + i * H_DIM;
    float acc[4][4] = {};
    for (int k0 = 0; k0 < H_DIM; k0 += 16) {
        float4 wv = *reinterpret_cast<const float4*>(&wrow[k0 + kq]);
        float4 av = *reinterpret_cast<const float4*>(&Sa[(bm+l4)*H_DIM + k0 + kq]);
        float4 bv = *reinterpret_cast<const float4*>(&Sb[(bn+l4)*H_DIM + k0 + kq]);
        As[kq+0][l4]=av.x*wv.x; As[kq+1][l4]=av.y*wv.y; As[kq+2][l4]=av.z*wv.z; As[kq+3][l4]=av.w*wv.w;
        Bs[kq+0][l4]=bv.x; Bs[kq+1][l4]=bv.y; Bs[kq+2][l4]=bv.z; Bs[kq+3][l4]=bv.w;
        __syncthreads();
        #pragma unroll
        for (int kk = 0; kk < 16; ++kk) {
            float4 a4 = *reinterpret_cast<const float4*>(&As[kk][ty*4]);
            float4 b4 = *reinterpret_cast<const float4*>(&Bs[kk][tx*4]);
            float a[4] = {a4.x,a4.y,a4.z,a4.w}, b[4] = {b4.x,b4.y,b4.z,b4.w};
            #pragma unroll
            for (int u = 0; u < 4; ++u)
                #pragma unroll
                for (int v = 0; v < 4; ++v) acc[u][v] = fmaf(a[u], b[v], acc[u][v]);
        }
        __syncthreads();
    }
    #pragma unroll
    for (int u = 0; u < 4; ++u) {
        int m = bm + ty*4 + u;
        const float* Pr = P + (size_t)m*N;
        const float* Qr = Q + (size_t)m*N;
        float* Kr = Kout + ((size_t)i*M + m)*N;
        #pragma unroll
        for (int v = 0; v < 4; ++v) {
            int n = bn + tx*4 + v;
            float val = SCALE_K * (Pr[n] + Qr[n]*acc[u][v]);
            if (addJitter && m == n) val += JITTER_K;
            Kr[n] = val;
        }
    }
}

// ---------------- Ktt diagonal per output ----------------
__global__ void kttd_kernel() {
    int i = blockIdx.x, t = threadIdx.x;
    const float* st = g_ST + t*H_DIM;
    const float* w  = g_W2SQT + i*H_DIM;
    float acc = 0.f;
    #pragma unroll 8
    for (int k = 0; k < H_DIM; ++k) { float s = st[k]; acc += s*s*w[k]; }
    g_Kttd[i*NT_PTS + t] = SCALE_K * (g_Ptt[t] + g_Qtt[t]*acc);
}

// ---------------- alpha_i = Kzx_i @ lambda1[:,i] ----------------
__global__ void alpha_kernel() {
    int gw = blockIdx.x * 8 + (threadIdx.x >> 5);
    int lane = threadIdx.x & 31;
    int i = gw >> 7, m = gw & 127;
    const float* row = g_Kzx + ((size_t)i*M_IND + m)*N_DATA;
    float acc = 0.f;
    for (int n = lane; n < N_DATA; n += 32) acc += row[n] * g_LAM[n*C_OUT + i];
    #pragma unroll
    for (int o = 16; o; o >>= 1) acc += __shfl_down_sync(0xffffffffu, acc, o);
    if (lane == 0) g_alpha[i*M_IND + m] = acc;
}

// ---------------- B_i = Kzz_i + 2 * Kzx_i @ Kzx_i^T ----------------
__global__ void bgemm_kernel() {
    __shared__ __align__(16) float As[16][68];
    __shared__ __align__(16) float Bs[16][68];
    const int i = blockIdx.z;
    const float* A = g_Kzx + (size_t)i*M_IND*N_DATA;
    const int tid = threadIdx.x;
    const int tx = tid & 15, ty = tid >> 4;
    const int bm = blockIdx.y * 64, bn = blockIdx.x * 64;
    const int l4 = tid >> 2, kq = (tid & 3) << 2;
    float acc[4][4] = {};
    for (int k0 = 0; k0 < N_DATA; k0 += 16) {
        float4 av = *reinterpret_cast<const float4*>(&A[(bm+l4)*N_DATA + k0 + kq]);
        float4 bv = *reinterpret_cast<const float4*>(&A[(bn+l4)*N_DATA + k0 + kq]);
        As[kq+0][l4]=av.x; As[kq+1][l4]=av.y; As[kq+2][l4]=av.z; As[kq+3][l4]=av.w;
        Bs[kq+0][l4]=bv.x; Bs[kq+1][l4]=bv.y; Bs[kq+2][l4]=bv.z; Bs[kq+3][l4]=bv.w;
        __syncthreads();
        #pragma unroll
        for (int kk = 0; kk < 16; ++kk) {
            float4 a4 = *reinterpret_cast<const float4*>(&As[kk][ty*4]);
            float4 b4 = *reinterpret_cast<const float4*>(&Bs[kk][tx*4]);
            float a[4] = {a4.x,a4.y,a4.z,a4.w}, b[4] = {b4.x,b4.y,b4.z,b4.w};
            #pragma unroll
            for (int u = 0; u < 4; ++u)
                #pragma unroll
                for (int v = 0; v < 4; ++v) acc[u][v] = fmaf(a[u], b[v], acc[u][v]);
        }
        __syncthreads();
    }
    #pragma unroll
    for (int u = 0; u < 4; ++u) {
        int m = bm + ty*4 + u;
        #pragma unroll
        for (int v = 0; v < 4; ++v) {
            int n = bn + tx*4 + v;
            size_t o = (size_t)i*M_IND*M_IND + m*M_IND + n;
            g_Bm[o] = g_Kzz[o] + 2.0f*acc[u][v];
        }
    }
}

// ---------------- batched 128x128 Cholesky (in-place lower) ----------------
__global__ void chol_kernel() {
    int s = blockIdx.x;
    float* A = (s < C_OUT) ? (g_Kzz + s*M_IND*M_IND) : (g_Bm + (s-C_OUT)*M_IND*M_IND);
    __shared__ float L[M_IND*(M_IND+1)/2];
    __shared__ float s_diag;
    int tid = threadIdx.x;
    for (int i = 0; i < M_IND; ++i)
        for (int j = tid; j <= i; j += 256) L[((i*(i+1))>>1) + j] = A[i*M_IND + j];
    __syncthreads();
    for (int j = 0; j < M_IND; ++j) {
        int i = j + tid;
        float sum = 0.f;
        if (i < M_IND) {
            const float* rowi = &L[(i*(i+1)) >> 1];
            const float* rowj = &L[(j*(j+1)) >> 1];
            sum = rowi[j];
            #pragma unroll 4
            for (int k = 0; k < j; ++k) sum -= rowi[k]*rowj[k];
            if (tid == 0) s_diag = sum;
        }
        __syncthreads();
        float d = sqrtf(s_diag);
        if (i < M_IND)
            L[((i*(i+1)) >> 1) + j] = (tid == 0) ? d : (sum / d);
        __syncthreads();
    }
    for (int i = 0; i < M_IND; ++i)
        for (int j = tid; j <= i; j += 256) A[i*M_IND + j] = L[((i*(i+1))>>1) + j];
}

// ---------------- forward solves: ss = ||L^{-1} k_t||^2 ----------------
__global__ void fs_kernel() {
    __shared__ float Lp[M_IND*(M_IND+1)/2];
    __shared__ float ys[8][M_IND];
    int tid = threadIdx.x, w = tid >> 5, lane = tid & 31;
    int s = blockIdx.x >> 5;            // 0..19
    int t = (blockIdx.x & 31)*8 + w;    // 0..255
    int i = (s < C_OUT) ? s : (s - C_OUT);
    const float* A = (s < C_OUT) ? (g_Kzz + s*M_IND*M_IND) : (g_Bm + (s-C_OUT)*M_IND*M_IND);
    for (int r = 0; r < M_IND; ++r)
        for (int j = tid; j <= r; j += 256) Lp[((r*(r+1))>>1) + j] = A[r*M_IND + j];
    __syncthreads();
    const float* bvec = g_Ktz + ((size_t)i*NT_PTS + t)*M_IND;
    float br[4];
    #pragma unroll
    for (int r = 0; r < 4; ++r) br[r] = bvec[lane + 32*r];
    float* y = ys[w];
    for (int j = 0; j < M_IND; ++j) {
        int base = (j*(j+1)) >> 1;
        float part = 0.f;
        for (int k = lane; k < j; k += 32) part += Lp[base + k] * y[k];
        #pragma unroll
        for (int o = 16; o; o >>= 1) part += __shfl_xor_sync(0xffffffffu, part, o);
        if (lane == (j & 31)) y[j] = (br[j >> 5] - part) / Lp[base + j];
        __syncwarp();
    }
    float ss = 0.f;
    #pragma unroll
    for (int r = 0; r < 4; ++r) { float v = y[lane + 32*r]; ss += v*v; }
    #pragma unroll
    for (int o = 16; o; o >>= 1) ss += __shfl_xor_sync(0xffffffffu, ss, o);
    if (lane == 0) {
        if (s < C_OUT) g_SSZ[i*NT_PTS + t] = ss;
        else           g_SSB[i*NT_PTS + t] = ss;
    }
}

// ---------------- c_i = B_i^{-1} alpha_i (fwd+bwd with L of B) ----------------
__global__ void meansolve_kernel() {
    __shared__ float Lp[M_IND*(M_IND+1)/2];
    __shared__ float y[M_IND];
    __shared__ float x[M_IND];
    int i = blockIdx.x, lane = threadIdx.x;
    const float* A = g_Bm + i*M_IND*M_IND;
    for (int r = 0; r < M_IND; ++r)
        for (int j = lane; j <= r; j += 32) Lp[((r*(r+1))>>1) + j] = A[r*M_IND + j];
    __syncwarp();
    float br[4];
    #pragma unroll
    for (int r = 0; r < 4; ++r) br[r] = g_alpha[i*M_IND + lane + 32*r];
    for (int j = 0; j < M_IND; ++j) {
        int base = (j*(j+1)) >> 1;
        float part = 0.f;
        for (int k = lane; k < j; k += 32) part += Lp[base + k] * y[k];
        #pragma unroll
        for (int o = 16; o; o >>= 1) part += __shfl_xor_sync(0xffffffffu, part, o);
        if (lane == (j & 31)) y[j] = (br[j >> 5] - part) / Lp[base + j];
        __syncwarp();
    }
    for (int j = M_IND-1; j >= 0; --j) {
        float part = 0.f;
        for (int k = j+1+lane; k < M_IND; k += 32) part += Lp[((k*(k+1))>>1) + j] * x[k];
        #pragma unroll
        for (int o = 16; o; o >>= 1) part += __shfl_xor_sync(0xffffffffu, part, o);
        if (lane == (j & 31)) x[j] = (y[j] - part) / Lp[((j*(j+1))>>1) + j];
        __syncwarp();
    }
    for (int r = lane; r < M_IND; r += 32) g_cvec[i*M_IND + r] = x[r];
}

// ---------------- mean = Ktz_i @ c_i ----------------
__global__ void mean_kernel(float* __restrict__ out) {
    int gw = blockIdx.x * 8 + (threadIdx.x >> 5);
    int lane = threadIdx.x & 31;
    if (gw >= NT_PTS*C_OUT) return;
    int t = gw / C_OUT, i = gw - t*C_OUT;
    const float* kr = g_Ktz + ((size_t)i*NT_PTS + t)*M_IND;
    const float* cr = g_cvec + i*M_IND;
    float acc = 0.f;
    #pragma unroll
    for (int r = 0; r < 4; ++r) acc += kr[lane + 32*r] * cr[lane + 32*r];
    #pragma unroll
    for (int o = 16; o; o >>= 1) acc += __shfl_down_sync(0xffffffffu, acc, o);
    if (lane == 0) out[t*C_OUT + i] = acc;
}

// ---------------- var = Kttd - ssKzz + ssB ----------------
__global__ void var_kernel(float* __restrict__ out) {
    int i = blockIdx.x, t = threadIdx.x;
    out[NT_PTS*C_OUT + t*C_OUT + i] =
        g_Kttd[i*NT_PTS + t] - g_SSZ[i*NT_PTS + t] + g_SSB[i*NT_PTS + t];
}

extern "C" void kernel_launch(void* const* d_in, const int* in_sizes, int n_in,
                              void* d_out, int out_size) {
    const float* X  = (const float*)d_in[0];
    const float* Y  = (const float*)d_in[1];
    const float* Z  = (const float*)d_in[2];
    const float* Xt = (const float*)d_in[3];
    const float* W1 = (const float*)d_in[4];
    const float* b1 = (const float*)d_in[5];
    const float* W2 = (const float*)d_in[6];
    const float* b2 = (const float*)d_in[7];
    float* out = (float*)d_out;

    float *pHX,*pSX,*pHZ,*pSZ,*pHT,*pST,*pPzx,*pQzx,*pPzz,*pQzz,*pPtz,*pQtz,*pKzx,*pKzz,*pKtz;
    cudaGetSymbolAddress((void**)&pHX,  g_HX);
    cudaGetSymbolAddress((void**)&pSX,  g_SX);
    cudaGetSymbolAddress((void**)&pHZ,  g_HZ);
    cudaGetSymbolAddress((void**)&pSZ,  g_SZ);
    cudaGetSymbolAddress((void**)&pHT,  g_HT);
    cudaGetSymbolAddress((void**)&pST,  g_ST);
    cudaGetSymbolAddress((void**)&pPzx, g_Pzx);
    cudaGetSymbolAddress((void**)&pQzx, g_Qzx);
    cudaGetSymbolAddress((void**)&pPzz, g_Pzz);
    cudaGetSymbolAddress((void**)&pQzz, g_Qzz);
    cudaGetSymbolAddress((void**)&pPtz, g_Ptz);
    cudaGetSymbolAddress((void**)&pQtz, g_Qtz);
    cudaGetSymbolAddress((void**)&pKzx, g_Kzx);
    cudaGetSymbolAddress((void**)&pKzz, g_Kzz);
    cudaGetSymbolAddress((void**)&pKtz, g_Ktz);

    prep_kernel<<<15, 256>>>(W2);
    fwd_kernel<<<dim3(6,16), 256>>>(X,  W1, b1, pHX, pSX);
    fwd_kernel<<<dim3(6,2),  256>>>(Z,  W1, b1, pHZ, pSZ);
    fwd_kernel<<<dim3(6,4),  256>>>(Xt, W1, b1, pHT, pST);
    lam_kernel<<<128, 256>>>(Y, W2, b2);
    pq_kernel<<<dim3(16,2), 256>>>(pHZ, pHX, Z,  X,  pPzx, pQzx, N_DATA);
    pq_kernel<<<dim3(2,2),  256>>>(pHZ, pHZ, Z,  Z,  pPzz, pQzz, M_IND);
    pq_kernel<<<dim3(2,4),  256>>>(pHT, pHZ, Xt, Z,  pPtz, pQtz, M_IND);
    pqtt_kernel<<<1, 256>>>(Xt);
    kbuild_kernel<<<dim3(16,2,10), 256>>>(pSZ, pSX, pPzx, pQzx, pKzx, M_IND,  N_DATA, 0);
    kbuild_kernel<<<dim3(2,2,10),  256>>>(pSZ, pSZ, pPzz, pQzz, pKzz, M_IND,  M_IND,  1);
    kbuild_kernel<<<dim3(2,4,10),  256>>>(pST, pSZ, pPtz, pQtz, pKtz, NT_PTS, M_IND,  0);
    kttd_kernel<<<10, 256>>>();
    alpha_kernel<<<160, 256>>>();
    bgemm_kernel<<<dim3(2,2,10), 256>>>();
    chol_kernel<<<20, 256>>>();
    fs_kernel<<<640, 256>>>();
    meansolve_kernel<<<10, 32>>>();
    mean_kernel<<<320, 256>>>(out);
    var_kernel<<<10, 256>>>(out);
}

// round 3
// speedup vs baseline: 2.7998x; 2.7998x over previous
#include <cuda_runtime.h>

#define N_DATA 1024
#define D_IN   256
#define H_DIM  384
#define C_OUT  10
#define M_IND  128
#define NT_PTS 256
#define SCALE_K (1.0f/1024.0f)
#define JITTER_K 1e-3f
#define LPACK (M_IND*(M_IND+1)/2)

// ---------------- device scratch ----------------
__device__ float g_HX[N_DATA*H_DIM];
__device__ float g_SX[N_DATA*H_DIM];
__device__ float g_HZ[M_IND*H_DIM];
__device__ float g_SZ[M_IND*H_DIM];
__device__ float g_HT[NT_PTS*H_DIM];
__device__ float g_ST[NT_PTS*H_DIM];
__device__ float g_LAM[N_DATA*C_OUT];
__device__ float g_Pzx[M_IND*N_DATA];
__device__ float g_Qzx[M_IND*N_DATA];
__device__ float g_Pzz[M_IND*M_IND];
__device__ float g_Qzz[M_IND*M_IND];
__device__ float g_Ptz[NT_PTS*M_IND];
__device__ float g_Qtz[NT_PTS*M_IND];
__device__ float g_Kzx[C_OUT*M_IND*N_DATA];
__device__ float g_Kzz[C_OUT*M_IND*M_IND];
__device__ float g_Ktz[C_OUT*NT_PTS*M_IND];
__device__ float g_Bpart[4*C_OUT*M_IND*M_IND];
__device__ float g_LKzz[C_OUT*LPACK];
__device__ float g_LB[C_OUT*LPACK];
__device__ float g_alpha[C_OUT*M_IND];
__device__ float g_cvec[C_OUT*M_IND];
__device__ float g_SSZ[C_OUT*NT_PTS];
__device__ float g_SSB[C_OUT*NT_PTS];

// =============== fused forward: H/S for X, Z, T (one launch) ===============
// grid (6, 22), 128 threads, 64x64 tile, 8x4 per thread, K=256
__global__ void fwd_all(const float* __restrict__ X, const float* __restrict__ Z,
                        const float* __restrict__ T, const float* __restrict__ W1,
                        const float* __restrict__ b1) {
    __shared__ __align__(16) float As[16][68];
    __shared__ __align__(16) float Bs[16][68];
    const int tid = threadIdx.x;
    const int rb = blockIdx.y, nb = blockIdx.x;
    const float* src; float* Hd; float* Sd; int row0;
    if (rb < 16)      { src = X; Hd = g_HX; Sd = g_SX; row0 = rb*64; }
    else if (rb < 18) { src = Z; Hd = g_HZ; Sd = g_SZ; row0 = (rb-16)*64; }
    else              { src = T; Hd = g_HT; Sd = g_ST; row0 = (rb-18)*64; }
    const int lrow = tid >> 1, lk = (tid & 1) << 3;
    const int kr = tid >> 3, nq = (tid & 7) << 3;
    const int tx = tid & 15, ty = tid >> 4;
    float acc[8][4] = {};
    for (int k0 = 0; k0 < D_IN; k0 += 16) {
        float4 a0 = *(const float4*)&src[(row0+lrow)*D_IN + k0 + lk];
        float4 a1 = *(const float4*)&src[(row0+lrow)*D_IN + k0 + lk + 4];
        float4 b0 = *(const float4*)&W1[(k0+kr)*H_DIM + nb*64 + nq];
        float4 b1v= *(const float4*)&W1[(k0+kr)*H_DIM + nb*64 + nq + 4];
        __syncthreads();
        As[lk+0][lrow]=a0.x; As[lk+1][lrow]=a0.y; As[lk+2][lrow]=a0.z; As[lk+3][lrow]=a0.w;
        As[lk+4][lrow]=a1.x; As[lk+5][lrow]=a1.y; As[lk+6][lrow]=a1.z; As[lk+7][lrow]=a1.w;
        *(float4*)&Bs[kr][nq] = b0; *(float4*)&Bs[kr][nq+4] = b1v;
        __syncthreads();
        #pragma unroll
        for (int kk = 0; kk < 16; ++kk) {
            float4 a4 = *(const float4*)&As[kk][ty*8];
            float4 a5 = *(const float4*)&As[kk][ty*8+4];
            float4 b4 = *(const float4*)&Bs[kk][tx*4];
            float a[8] = {a4.x,a4.y,a4.z,a4.w,a5.x,a5.y,a5.z,a5.w};
            float b[4] = {b4.x,b4.y,b4.z,b4.w};
            #pragma unroll
            for (int u = 0; u < 8; ++u)
                #pragma unroll
                for (int v = 0; v < 4; ++v) acc[u][v] = fmaf(a[u], b[v], acc[u][v]);
        }
    }
    const int n0 = nb*64 + tx*4;
    float4 bv = *(const float4*)&b1[n0];
    #pragma unroll
    for (int u = 0; u < 8; ++u) {
        int m = row0 + ty*8 + u;
        float4 h4, s4;
        h4.x = tanhf(acc[u][0]+bv.x); h4.y = tanhf(acc[u][1]+bv.y);
        h4.z = tanhf(acc[u][2]+bv.z); h4.w = tanhf(acc[u][3]+bv.w);
        s4.x = 1.f-h4.x*h4.x; s4.y = 1.f-h4.y*h4.y;
        s4.z = 1.f-h4.z*h4.z; s4.w = 1.f-h4.w*h4.w;
        *(float4*)&Hd[m*H_DIM + n0] = h4;
        *(float4*)&Sd[m*H_DIM + n0] = s4;
    }
}

// =============== lambda1 = F + Y ===============
__global__ void lam_kernel(const float* __restrict__ Y, const float* __restrict__ W2,
                           const float* __restrict__ b2) {
    int warp = threadIdx.x >> 5, lane = threadIdx.x & 31;
    int row = blockIdx.x * 8 + warp;
    float h[12];
    #pragma unroll
    for (int r = 0; r < 12; ++r) h[r] = g_HX[row*H_DIM + lane + r*32];
    #pragma unroll
    for (int c = 0; c < C_OUT; ++c) {
        float acc = 0.f;
        #pragma unroll
        for (int r = 0; r < 12; ++r) acc += h[r] * W2[(lane + r*32)*C_OUT + c];
        #pragma unroll
        for (int o = 16; o; o >>= 1) acc += __shfl_down_sync(0xffffffffu, acc, o);
        if (lane == 0) g_LAM[row*C_OUT + c] = acc + b2[c] + Y[row*C_OUT + c];
    }
}

// =============== P and Q grams, all pairs, split into 88 jobs ===============
__global__ void pq_all(const float* __restrict__ X, const float* __restrict__ Z,
                       const float* __restrict__ T) {
    __shared__ __align__(16) float As[16][68];
    __shared__ __align__(16) float Bs[16][68];
    const int tid = threadIdx.x;
    int j = blockIdx.x;
    const int isQ = (j >= 44); if (isQ) j -= 44;
    const float *Ap, *Bp; float* outp; int Nc, mt, nt;
    if (j < 32)      { mt=j>>4;      nt=j&15;     Ap=isQ?Z:g_HZ; Bp=isQ?X:g_HX; outp=isQ?g_Qzx:g_Pzx; Nc=N_DATA; }
    else if (j < 36) { mt=(j-32)>>1; nt=(j-32)&1; Ap=isQ?Z:g_HZ; Bp=isQ?Z:g_HZ; outp=isQ?g_Qzz:g_Pzz; Nc=M_IND; }
    else             { mt=(j-36)>>1; nt=(j-36)&1; Ap=isQ?T:g_HT; Bp=isQ?Z:g_HZ; outp=isQ?g_Qtz:g_Ptz; Nc=M_IND; }
    const int K = isQ ? D_IN : H_DIM;   // row strides equal K for both sources
    const int bm = mt*64, bn = nt*64;
    const int lrow = tid >> 1, lk = (tid & 1) << 3;
    const int tx = tid & 15, ty = tid >> 4;
    float acc[8][4] = {};
    for (int k0 = 0; k0 < K; k0 += 16) {
        float4 a0 = *(const float4*)&Ap[(bm+lrow)*K + k0 + lk];
        float4 a1 = *(const float4*)&Ap[(bm+lrow)*K + k0 + lk + 4];
        float4 b0 = *(const float4*)&Bp[(bn+lrow)*K + k0 + lk];
        float4 b1 = *(const float4*)&Bp[(bn+lrow)*K + k0 + lk + 4];
        __syncthreads();
        As[lk+0][lrow]=a0.x; As[lk+1][lrow]=a0.y; As[lk+2][lrow]=a0.z; As[lk+3][lrow]=a0.w;
        As[lk+4][lrow]=a1.x; As[lk+5][lrow]=a1.y; As[lk+6][lrow]=a1.z; As[lk+7][lrow]=a1.w;
        Bs[lk+0][lrow]=b0.x; Bs[lk+1][lrow]=b0.y; Bs[lk+2][lrow]=b0.z; Bs[lk+3][lrow]=b0.w;
        Bs[lk+4][lrow]=b1.x; Bs[lk+5][lrow]=b1.y; Bs[lk+6][lrow]=b1.z; Bs[lk+7][lrow]=b1.w;
        __syncthreads();
        #pragma unroll
        for (int kk = 0; kk < 16; ++kk) {
            float4 a4 = *(const float4*)&As[kk][ty*8];
            float4 a5 = *(const float4*)&As[kk][ty*8+4];
            float4 b4 = *(const float4*)&Bs[kk][tx*4];
            float a[8] = {a4.x,a4.y,a4.z,a4.w,a5.x,a5.y,a5.z,a5.w};
            float b[4] = {b4.x,b4.y,b4.z,b4.w};
            #pragma unroll
            for (int u = 0; u < 8; ++u)
                #pragma unroll
                for (int v = 0; v < 4; ++v) acc[u][v] = fmaf(a[u], b[v], acc[u][v]);
        }
    }
    const int n0 = bn + tx*4;
    #pragma unroll
    for (int u = 0; u < 8; ++u) {
        int m = bm + ty*8 + u;
        float4 o4 = {acc[u][0]+1.f, acc[u][1]+1.f, acc[u][2]+1.f, acc[u][3]+1.f};
        *(float4*)&outp[(size_t)m*Nc + n0] = o4;
    }
}

// =============== all 30 K matrices in one launch (440 jobs) ===============
__global__ void kbuild_all(const float* __restrict__ W2) {
    __shared__ __align__(16) float As[16][68];
    __shared__ __align__(16) float Bs[16][68];
    __shared__ float ws[H_DIM];
    const int tid = threadIdx.x;
    const int j = blockIdx.x;
    const float *Sa, *Sb, *Pp, *Qp; float* Kout; int Nc, mt, nt, i, jit;
    if (j < 320)      { i=j>>5; int r=j&31; mt=r>>4; nt=r&15; Sa=g_SZ; Sb=g_SX; Pp=g_Pzx; Qp=g_Qzx; Kout=g_Kzx+(size_t)i*M_IND*N_DATA; Nc=N_DATA; jit=0; }
    else if (j < 360) { i=(j-320)>>2; int r=(j-320)&3; mt=r>>1; nt=r&1; Sa=g_SZ; Sb=g_SZ; Pp=g_Pzz; Qp=g_Qzz; Kout=g_Kzz+(size_t)i*M_IND*M_IND; Nc=M_IND; jit=1; }
    else              { i=(j-360)>>3; int r=(j-360)&7; mt=r>>1; nt=r&1; Sa=g_ST; Sb=g_SZ; Pp=g_Ptz; Qp=g_Qtz; Kout=g_Ktz+(size_t)i*NT_PTS*M_IND; Nc=M_IND; jit=0; }
    for (int k = tid; k < H_DIM; k += 128) { float w = W2[k*C_OUT + i]; ws[k] = w*w; }
    const int bm = mt*64, bn = nt*64;
    const int lrow = tid >> 1, lk = (tid & 1) << 3;
    const int tx = tid & 15, ty = tid >> 4;
    float acc[8][4] = {};
    for (int k0 = 0; k0 < H_DIM; k0 += 16) {
        float4 a0 = *(const float4*)&Sa[(bm+lrow)*H_DIM + k0 + lk];
        float4 a1 = *(const float4*)&Sa[(bm+lrow)*H_DIM + k0 + lk + 4];
        float4 b0 = *(const float4*)&Sb[(bn+lrow)*H_DIM + k0 + lk];
        float4 b1 = *(const float4*)&Sb[(bn+lrow)*H_DIM + k0 + lk + 4];
        __syncthreads();
        As[lk+0][lrow]=a0.x*ws[k0+lk+0]; As[lk+1][lrow]=a0.y*ws[k0+lk+1];
        As[lk+2][lrow]=a0.z*ws[k0+lk+2]; As[lk+3][lrow]=a0.w*ws[k0+lk+3];
        As[lk+4][lrow]=a1.x*ws[k0+lk+4]; As[lk+5][lrow]=a1.y*ws[k0+lk+5];
        As[lk+6][lrow]=a1.z*ws[k0+lk+6]; As[lk+7][lrow]=a1.w*ws[k0+lk+7];
        Bs[lk+0][lrow]=b0.x; Bs[lk+1][lrow]=b0.y; Bs[lk+2][lrow]=b0.z; Bs[lk+3][lrow]=b0.w;
        Bs[lk+4][lrow]=b1.x; Bs[lk+5][lrow]=b1.y; Bs[lk+6][lrow]=b1.z; Bs[lk+7][lrow]=b1.w;
        __syncthreads();
        #pragma unroll
        for (int kk = 0; kk < 16; ++kk) {
            float4 a4 = *(const float4*)&As[kk][ty*8];
            float4 a5 = *(const float4*)&As[kk][ty*8+4];
            float4 b4 = *(const float4*)&Bs[kk][tx*4];
            float a[8] = {a4.x,a4.y,a4.z,a4.w,a5.x,a5.y,a5.z,a5.w};
            float b[4] = {b4.x,b4.y,b4.z,b4.w};
            #pragma unroll
            for (int u = 0; u < 8; ++u)
                #pragma unroll
                for (int v = 0; v < 4; ++v) acc[u][v] = fmaf(a[u], b[v], acc[u][v]);
        }
    }
    const int n0 = bn + tx*4;
    #pragma unroll
    for (int u = 0; u < 8; ++u) {
        int m = bm + ty*8 + u;
        float4 p4 = *(const float4*)&Pp[(size_t)m*Nc + n0];
        float4 q4 = *(const float4*)&Qp[(size_t)m*Nc + n0];
        float4 o4;
        o4.x = SCALE_K*(p4.x + q4.x*acc[u][0]);
        o4.y = SCALE_K*(p4.y + q4.y*acc[u][1]);
        o4.z = SCALE_K*(p4.z + q4.z*acc[u][2]);
        o4.w = SCALE_K*(p4.w + q4.w*acc[u][3]);
        if (jit && m >= n0 && m < n0+4) {
            if (m == n0)   o4.x += JITTER_K;
            if (m == n0+1) o4.y += JITTER_K;
            if (m == n0+2) o4.z += JITTER_K;
            if (m == n0+3) o4.w += JITTER_K;
        }
        *(float4*)&Kout[(size_t)m*Nc + n0] = o4;
    }
}

// =============== Bpart (split-K of 2*Kzx@Kzx^T) + alpha, one launch ===============
__global__ void bgemm_alpha() {
    const int tid = threadIdx.x;
    const int j = blockIdx.x;
    if (j < 160) {
        __shared__ __align__(16) float As[16][68];
        __shared__ __align__(16) float Bs[16][68];
        int i = j >> 4, r = j & 15;
        int kc = r >> 2, mt = (r >> 1) & 1, nt = r & 1;
        const float* A = g_Kzx + (size_t)i*M_IND*N_DATA;
        const int bm = mt*64, bn = nt*64, kbeg = kc*256;
        const int lrow = tid >> 1, lk = (tid & 1) << 3;
        const int tx = tid & 15, ty = tid >> 4;
        float acc[8][4] = {};
        for (int k0 = kbeg; k0 < kbeg+256; k0 += 16) {
            float4 a0 = *(const float4*)&A[(bm+lrow)*N_DATA + k0 + lk];
            float4 a1 = *(const float4*)&A[(bm+lrow)*N_DATA + k0 + lk + 4];
            float4 b0 = *(const float4*)&A[(bn+lrow)*N_DATA + k0 + lk];
            float4 b1 = *(const float4*)&A[(bn+lrow)*N_DATA + k0 + lk + 4];
            __syncthreads();
            As[lk+0][lrow]=a0.x; As[lk+1][lrow]=a0.y; As[lk+2][lrow]=a0.z; As[lk+3][lrow]=a0.w;
            As[lk+4][lrow]=a1.x; As[lk+5][lrow]=a1.y; As[lk+6][lrow]=a1.z; As[lk+7][lrow]=a1.w;
            Bs[lk+0][lrow]=b0.x; Bs[lk+1][lrow]=b0.y; Bs[lk+2][lrow]=b0.z; Bs[lk+3][lrow]=b0.w;
            Bs[lk+4][lrow]=b1.x; Bs[lk+5][lrow]=b1.y; Bs[lk+6][lrow]=b1.z; Bs[lk+7][lrow]=b1.w;
            __syncthreads();
            #pragma unroll
            for (int kk = 0; kk < 16; ++kk) {
                float4 a4 = *(const float4*)&As[kk][ty*8];
                float4 a5 = *(const float4*)&As[kk][ty*8+4];
                float4 b4 = *(const float4*)&Bs[kk][tx*4];
                float a[8] = {a4.x,a4.y,a4.z,a4.w,a5.x,a5.y,a5.z,a5.w};
                float b[4] = {b4.x,b4.y,b4.z,b4.w};
                #pragma unroll
                for (int u = 0; u < 8; ++u)
                    #pragma unroll
                    for (int v = 0; v < 4; ++v) acc[u][v] = fmaf(a[u], b[v], acc[u][v]);
            }
        }
        float* outp = g_Bpart + ((size_t)(kc*C_OUT + i)*M_IND)*M_IND;
        const int n0 = bn + tx*4;
        #pragma unroll
        for (int u = 0; u < 8; ++u) {
            int m = bm + ty*8 + u;
            float4 o4 = {2.f*acc[u][0], 2.f*acc[u][1], 2.f*acc[u][2], 2.f*acc[u][3]};
            *(float4*)&outp[m*M_IND + n0] = o4;
        }
    } else {
        int k = j - 160;
        int i = k >> 2, rb = (k & 3) * 32;
        int w = tid >> 5, lane = tid & 31;
        #pragma unroll
        for (int rr = 0; rr < 8; ++rr) {
            int m = rb + w*8 + rr;
            const float* row = g_Kzx + ((size_t)i*M_IND + m)*N_DATA;
            float acc = 0.f;
            for (int n = lane; n < N_DATA; n += 32) acc += row[n] * g_LAM[n*C_OUT + i];
            #pragma unroll
            for (int o = 16; o; o >>= 1) acc += __shfl_down_sync(0xffffffffu, acc, o);
            if (lane == 0) g_alpha[i*M_IND + m] = acc;
        }
    }
}

// =============== batched Cholesky of Kzz and B=Kzz+sum(Bpart) ===============
__global__ void chol_all() {
    const int s = blockIdx.x, tid = threadIdx.x;
    const int isB = (s >= C_OUT);
    const int i = isB ? s - C_OUT : s;
    const float* A0 = g_Kzz + (size_t)i*M_IND*M_IND;
    __shared__ float L[LPACK];
    __shared__ float s_diag;
    for (int r = 0; r < M_IND; ++r)
        for (int c = tid; c <= r; c += 256) {
            float v = A0[r*M_IND + c];
            if (isB) {
                #pragma unroll
                for (int p = 0; p < 4; ++p)
                    v += g_Bpart[((size_t)(p*C_OUT + i)*M_IND + r)*M_IND + c];
            }
            L[((r*(r+1))>>1) + c] = v;
        }
    __syncthreads();
    for (int jc = 0; jc < M_IND; ++jc) {
        int ir = jc + tid;
        float sum = 0.f;
        if (ir < M_IND) {
            const float* ri = &L[(ir*(ir+1)) >> 1];
            const float* rj = &L[(jc*(jc+1)) >> 1];
            float s0=0,s1=0,s2=0,s3=0; int k = 0;
            for (; k+4 <= jc; k += 4) {
                s0 += ri[k]*rj[k];   s1 += ri[k+1]*rj[k+1];
                s2 += ri[k+2]*rj[k+2]; s3 += ri[k+3]*rj[k+3];
            }
            for (; k < jc; ++k) s0 += ri[k]*rj[k];
            sum = ri[jc] - ((s0+s1)+(s2+s3));
            if (tid == 0) s_diag = sum;
        }
        __syncthreads();
        float d = sqrtf(s_diag);
        if (ir < M_IND) L[((ir*(ir+1))>>1) + jc] = (tid == 0) ? d : (sum / d);
        __syncthreads();
    }
    float* out = isB ? (g_LB + i*LPACK) : (g_LKzz + i*LPACK);
    for (int idx = tid; idx < LPACK; idx += 256) out[idx] = L[idx];
}

// =============== solves: 640 fs blocks + 10 meansolve blocks ===============
__global__ void solve_all() {
    __shared__ float Lp[LPACK];
    __shared__ float dinv[M_IND];
    __shared__ float ysm[M_IND];
    const int b = blockIdx.x, tid = threadIdx.x;
    const int w = tid >> 5, lane = tid & 31;
    if (b < 640) {
        const int s = b >> 5;
        const int t = (b & 31)*8 + w;
        const int i = (s < C_OUT) ? s : s - C_OUT;
        const float* Ls = (s < C_OUT) ? (g_LKzz + s*LPACK) : (g_LB + (s-C_OUT)*LPACK);
        for (int idx = tid; idx < LPACK; idx += 256) Lp[idx] = Ls[idx];
        if (tid < M_IND) dinv[tid] = 1.0f / Ls[((tid*(tid+1))>>1) + tid];
        __syncthreads();
        const float* bvec = g_Ktz + ((size_t)i*NT_PTS + t)*M_IND;
        float br[4];
        int base[4];
        #pragma unroll
        for (int r = 0; r < 4; ++r) {
            br[r] = bvec[lane + 32*r];
            int row = r*32 + lane;
            base[r] = (row*(row+1)) >> 1;
        }
        float ss = 0.f;
        #pragma unroll
        for (int oreg = 0; oreg < 4; ++oreg) {
            for (int jj = 0; jj < 32; ++jj) {
                int jc = oreg*32 + jj;
                float yj = __shfl_sync(0xffffffffu, br[oreg], jj) * dinv[jc];
                ss = fmaf(yj, yj, ss);
                if (lane > jj) br[oreg] -= Lp[base[oreg] + jc] * yj;
                #pragma unroll
                for (int r = oreg+1; r < 4; ++r) br[r] -= Lp[base[r] + jc] * yj;
            }
        }
        if (lane == 0) {
            if (s < C_OUT) g_SSZ[i*NT_PTS + t] = ss;
            else           g_SSB[i*NT_PTS + t] = ss;
        }
    } else {
        const int i = b - 640;
        const float* Ls = g_LB + i*LPACK;
        for (int idx = tid; idx < LPACK; idx += 256) Lp[idx] = Ls[idx];
        if (tid < M_IND) dinv[tid] = 1.0f / Ls[((tid*(tid+1))>>1) + tid];
        __syncthreads();
        if (w != 0) return;
        float br[4];
        int base[4];
        #pragma unroll
        for (int r = 0; r < 4; ++r) {
            br[r] = g_alpha[i*M_IND + lane + 32*r];
            int row = r*32 + lane;
            base[r] = (row*(row+1)) >> 1;
        }
        #pragma unroll
        for (int oreg = 0; oreg < 4; ++oreg) {
            for (int jj = 0; jj < 32; ++jj) {
                int jc = oreg*32 + jj;
                float yj = __shfl_sync(0xffffffffu, br[oreg], jj) * dinv[jc];
                if (lane == 0) ysm[jc] = yj;
                if (lane > jj) br[oreg] -= Lp[base[oreg] + jc] * yj;
                #pragma unroll
                for (int r = oreg+1; r < 4; ++r) br[r] -= Lp[base[r] + jc] * yj;
            }
        }
        __syncwarp();
        float xr[4];
        #pragma unroll
        for (int r = 0; r < 4; ++r) xr[r] = ysm[r*32 + lane];
        #pragma unroll
        for (int oreg = 3; oreg >= 0; --oreg) {
            for (int jj = 31; jj >= 0; --jj) {
                int jc = oreg*32 + jj;
                float xj = __shfl_sync(0xffffffffu, xr[oreg], jj) * dinv[jc];
                if (lane == 0) g_cvec[i*M_IND + jc] = xj;
                int rb2 = (jc*(jc+1)) >> 1;
                if (lane < jj) xr[oreg] -= Lp[rb2 + oreg*32 + lane] * xj;
                #pragma unroll
                for (int r = 0; r < 4; ++r)
                    if (r < oreg) xr[r] -= Lp[rb2 + r*32 + lane] * xj;
            }
        }
    }
}

// =============== epilogue: mean + variance ===============
__global__ void epilogue(const float* __restrict__ Xt, const float* __restrict__ W2,
                         float* __restrict__ out) {
    const int gw = blockIdx.x*8 + (threadIdx.x >> 5);
    const int lane = threadIdx.x & 31;
    const int t = gw / C_OUT, i = gw - t*C_OUT;
    float accU = 0.f, ph = 0.f, qx = 0.f;
    for (int k = lane; k < H_DIM; k += 32) {
        float s = g_ST[t*H_DIM + k];
        float h = g_HT[t*H_DIM + k];
        float w = W2[k*C_OUT + i];
        accU = fmaf(s*s, w*w, accU);
        ph = fmaf(h, h, ph);
    }
    for (int k = lane; k < D_IN; k += 32) { float x = Xt[t*D_IN + k]; qx = fmaf(x, x, qx); }
    float mean = 0.f;
    const float* kr = g_Ktz + ((size_t)i*NT_PTS + t)*M_IND;
    const float* cr = g_cvec + i*M_IND;
    #pragma unroll
    for (int r = 0; r < 4; ++r) mean += kr[lane + 32*r] * cr[lane + 32*r];
    #pragma unroll
    for (int o = 16; o; o >>= 1) {
        accU += __shfl_xor_sync(0xffffffffu, accU, o);
        ph   += __shfl_xor_sync(0xffffffffu, ph, o);
        qx   += __shfl_xor_sync(0xffffffffu, qx, o);
        mean += __shfl_xor_sync(0xffffffffu, mean, o);
    }
    if (lane == 0) {
        float kttd = SCALE_K * ((ph + 1.f) + (qx + 1.f)*accU);
        out[t*C_OUT + i] = mean;
        out[NT_PTS*C_OUT + t*C_OUT + i] = kttd - g_SSZ[i*NT_PTS + t] + g_SSB[i*NT_PTS + t];
    }
}

extern "C" void kernel_launch(void* const* d_in, const int* in_sizes, int n_in,
                              void* d_out, int out_size) {
    const float* X  = (const float*)d_in[0];
    const float* Y  = (const float*)d_in[1];
    const float* Z  = (const float*)d_in[2];
    const float* Xt = (const float*)d_in[3];
    const float* W1 = (const float*)d_in[4];
    const float* b1 = (const float*)d_in[5];
    const float* W2 = (const float*)d_in[6];
    const float* b2 = (const float*)d_in[7];
    float* out = (float*)d_out;

    fwd_all<<<dim3(6,22), 128>>>(X, Z, Xt, W1, b1);
    lam_kernel<<<128, 256>>>(Y, W2, b2);
    pq_all<<<88, 128>>>(X, Z, Xt);
    kbuild_all<<<440, 128>>>(W2);
    bgemm_alpha<<<200, 128>>>();
    chol_all<<<20, 256>>>();
    solve_all<<<650, 256>>>();
    epilogue<<<320, 256>>>(Xt, W2, out);
}